// round 6
// baseline (speedup 1.0000x reference)
#include <cuda_runtime.h>
#include <cstdint>

// Problem constants
#define BB 32
#define TT 512
#define HH 1024
#define G4 4096   // 4*H

// ---------------- scratch (static device memory; no allocs allowed) ---------
__device__ float g_xg[(size_t)16384 * 4096];   // [B*T, 4H] pre-activations (reused by both layers)
__device__ float g_h0[(size_t)16384 * 1024];   // layer-0 hidden sequence [B*T, H]
__device__ float g_hbuf[BB * HH];              // current h broadcast buffer [32,1024]
__device__ unsigned g_bar[2];                  // {count, generation}

// ---------------- helpers ---------------------------------------------------
__device__ __forceinline__ unsigned tf32r(float f) {
    unsigned r;
    asm("cvt.rna.tf32.f32 %0, %1;" : "=r"(r) : "f"(f));
    return r;
}

__device__ __forceinline__ void mma8(float* d, const unsigned* a, const unsigned* b, const float* c) {
    asm volatile(
        "mma.sync.aligned.m16n8k8.row.col.f32.tf32.tf32.f32 "
        "{%0,%1,%2,%3},{%4,%5,%6,%7},{%8,%9},{%10,%11,%12,%13};\n"
        : "=f"(d[0]), "=f"(d[1]), "=f"(d[2]), "=f"(d[3])
        : "r"(a[0]), "r"(a[1]), "r"(a[2]), "r"(a[3]),
          "r"(b[0]), "r"(b[1]),
          "f"(c[0]), "f"(c[1]), "f"(c[2]), "f"(c[3]));
}

__device__ __forceinline__ void grid_barrier(unsigned target) {
    __threadfence();
    __syncthreads();
    if (threadIdx.x == 0) {
        unsigned old = atomicAdd(&g_bar[0], 1u);
        if (old == gridDim.x - 1) {
            atomicExch(&g_bar[0], 0u);
            __threadfence();
            atomicExch(&g_bar[1], target);
        } else {
            while (*((volatile unsigned*)&g_bar[1]) < target) { }
        }
    }
    __syncthreads();
}

// ---------------- big GEMM: C[M,4096] = A[M,1024] @ W[4096,1024]^T + (b1+b2) -
// BM=128, BN=128, BK=16, 256 threads, tf32 mma, double-buffered smem.
__global__ __launch_bounds__(256)
void gemm_xw_bias(const float* __restrict__ A, const float* __restrict__ W,
                  const float* __restrict__ b1, const float* __restrict__ b2,
                  float* __restrict__ C) {
    const int K = 1024, N = 4096;
    __shared__ float sA[2][128][20];
    __shared__ float sB[2][128][20];

    const int tid = threadIdx.x;
    const int mBase = blockIdx.y * 128, nBase = blockIdx.x * 128;
    const int warp = tid >> 5, lane = tid & 31;
    const int g = lane >> 2, tg = lane & 3;
    const int m_off = (warp & 3) * 32;   // 4 warps along M
    const int n_off = (warp >> 2) * 64;  // 2 warps along N

    float acc[2][8][4];
#pragma unroll
    for (int mt = 0; mt < 2; mt++)
#pragma unroll
        for (int nt = 0; nt < 8; nt++)
#pragma unroll
            for (int e = 0; e < 4; e++) acc[mt][nt][e] = 0.f;

    float4 ra[2], rb[2];
    const int row0 = tid >> 2, c40 = tid & 3;           // j=0 mapping
    const int row1 = (tid + 256) >> 2, c41 = tid & 3;   // j=1 mapping

#define FETCH(kt)                                                                     \
    do {                                                                              \
        ra[0] = *(const float4*)(A + (size_t)(mBase + row0) * K + (kt) * 16 + c40*4); \
        rb[0] = *(const float4*)(W + (size_t)(nBase + row0) * K + (kt) * 16 + c40*4); \
        ra[1] = *(const float4*)(A + (size_t)(mBase + row1) * K + (kt) * 16 + c41*4); \
        rb[1] = *(const float4*)(W + (size_t)(nBase + row1) * K + (kt) * 16 + c41*4); \
    } while (0)

#define STORE(bf)                                                                 \
    do {                                                                          \
        float* pa0 = &sA[bf][row0][c40 * 4]; float* pb0 = &sB[bf][row0][c40 * 4]; \
        pa0[0]=__uint_as_float(tf32r(ra[0].x)); pa0[1]=__uint_as_float(tf32r(ra[0].y)); \
        pa0[2]=__uint_as_float(tf32r(ra[0].z)); pa0[3]=__uint_as_float(tf32r(ra[0].w)); \
        pb0[0]=__uint_as_float(tf32r(rb[0].x)); pb0[1]=__uint_as_float(tf32r(rb[0].y)); \
        pb0[2]=__uint_as_float(tf32r(rb[0].z)); pb0[3]=__uint_as_float(tf32r(rb[0].w)); \
        float* pa1 = &sA[bf][row1][c41 * 4]; float* pb1 = &sB[bf][row1][c41 * 4]; \
        pa1[0]=__uint_as_float(tf32r(ra[1].x)); pa1[1]=__uint_as_float(tf32r(ra[1].y)); \
        pa1[2]=__uint_as_float(tf32r(ra[1].z)); pa1[3]=__uint_as_float(tf32r(ra[1].w)); \
        pb1[0]=__uint_as_float(tf32r(rb[1].x)); pb1[1]=__uint_as_float(tf32r(rb[1].y)); \
        pb1[2]=__uint_as_float(tf32r(rb[1].z)); pb1[3]=__uint_as_float(tf32r(rb[1].w)); \
    } while (0)

    FETCH(0);
    STORE(0);
    __syncthreads();

    for (int kt = 0; kt < 64; kt++) {
        const int cur = kt & 1;
        if (kt < 63) FETCH(kt + 1);
#pragma unroll
        for (int ks = 0; ks < 2; ks++) {
            const int k0 = ks * 8;
            unsigned afr[2][4], bfr[8][2];
#pragma unroll
            for (int mt = 0; mt < 2; mt++) {
                const int r = m_off + mt * 16 + g;
                afr[mt][0] = __float_as_uint(sA[cur][r][k0 + tg]);
                afr[mt][1] = __float_as_uint(sA[cur][r + 8][k0 + tg]);
                afr[mt][2] = __float_as_uint(sA[cur][r][k0 + tg + 4]);
                afr[mt][3] = __float_as_uint(sA[cur][r + 8][k0 + tg + 4]);
            }
#pragma unroll
            for (int nt = 0; nt < 8; nt++) {
                const int n = n_off + nt * 8 + g;
                bfr[nt][0] = __float_as_uint(sB[cur][n][k0 + tg]);
                bfr[nt][1] = __float_as_uint(sB[cur][n][k0 + tg + 4]);
            }
#pragma unroll
            for (int mt = 0; mt < 2; mt++)
#pragma unroll
                for (int nt = 0; nt < 8; nt++)
                    mma8(acc[mt][nt], afr[mt], bfr[nt], acc[mt][nt]);
        }
        if (kt < 63) STORE(cur ^ 1);
        __syncthreads();
    }
#undef FETCH
#undef STORE

    // epilogue: += (b1+b2)
#pragma unroll
    for (int mt = 0; mt < 2; mt++) {
#pragma unroll
        for (int nt = 0; nt < 8; nt++) {
            const int r0 = mBase + m_off + mt * 16 + g;
            const int c0 = nBase + n_off + nt * 8 + 2 * tg;
            const float bs0 = __ldg(b1 + c0) + __ldg(b2 + c0);
            const float bs1 = __ldg(b1 + c0 + 1) + __ldg(b2 + c0 + 1);
            C[(size_t)r0 * N + c0]           = acc[mt][nt][0] + bs0;
            C[(size_t)r0 * N + c0 + 1]       = acc[mt][nt][1] + bs1;
            C[(size_t)(r0 + 8) * N + c0]     = acc[mt][nt][2] + bs0;
            C[(size_t)(r0 + 8) * N + c0 + 1] = acc[mt][nt][3] + bs1;
        }
    }
}

// ---------------- persistent LSTM layer -------------------------------------
// 128 CTAs (1/SM, all resident), 256 threads. CTA c owns hidden units
// [c*8, c*8+8) -> 32 gate columns {gi*1024 + ubase + u}. Whh slice cached in
// SMEM (tf32-rounded). Per step: gates = xg[t] + h @ Whh_slice^T (tf32 mma,
// K split across warp halves), cell update, h broadcast via gmem, grid barrier.
#define LSTM_NCTA 128
#define SW_STRIDE 1028
#define SH_STRIDE 132
#define SMEM_LSTM_FLOATS (32 * SW_STRIDE + 2 * 32 * SH_STRIDE + 2 * 32 * 32)
#define SMEM_LSTM_BYTES (SMEM_LSTM_FLOATS * 4)

__global__ __launch_bounds__(256)
void lstm_layer_kernel(const float* __restrict__ xg, const float* __restrict__ Whh,
                       float* __restrict__ seq_out, const float* __restrict__ resid,
                       int has_resid) {
    extern __shared__ float sm[];
    float* sW = sm;                         // [32][1028]
    float* sH = sW + 32 * SW_STRIDE;        // [2][32][132]
    float* sP = sH + 2 * 32 * SH_STRIDE;    // [2][32][32]

    const int tid = threadIdx.x;
    const int warp = tid >> 5, lane = tid & 31;
    const int g = lane >> 2, tg = lane & 3;
    const int n_off = (warp & 3) * 8;
    const int khalf = warp >> 2;
    const int ubase = blockIdx.x * 8;
    const int b = tid >> 3, u = tid & 7;

    // load + tf32-round the Whh slice (32 rows x 1024) into smem
    for (int i = tid; i < 32 * 256; i += 256) {
        const int col = i >> 8;      // 0..31
        const int f4 = i & 255;      // 0..255
        const int grow = (col >> 3) * 1024 + ubase + (col & 7);
        float4 v = *(const float4*)(Whh + (size_t)grow * 1024 + f4 * 4);
        float* dst = sW + col * SW_STRIDE + f4 * 4;
        dst[0] = __uint_as_float(tf32r(v.x));
        dst[1] = __uint_as_float(tf32r(v.y));
        dst[2] = __uint_as_float(tf32r(v.z));
        dst[3] = __uint_as_float(tf32r(v.w));
    }
    // zero my slice of the h broadcast buffer
    g_hbuf[b * HH + ubase + u] = 0.f;

    unsigned bt = 0;
    grid_barrier(++bt);

    const int srow = tid >> 5 ? 0 : 0; (void)srow;
    float c_state = 0.f;

    for (int t = 0; t < TT; t++) {
        // prefetch this thread's 4 gate pre-activations (DRAM; consumed ~2us later)
        const size_t xrow = (size_t)(b * TT + t) * G4;
        const float xp0 = __ldg(xg + xrow + 0 * HH + ubase + u);
        const float xp1 = __ldg(xg + xrow + 1 * HH + ubase + u);
        const float xp2 = __ldg(xg + xrow + 2 * HH + ubase + u);
        const float xp3 = __ldg(xg + xrow + 3 * HH + ubase + u);

        float acc[2][4];
#pragma unroll
        for (int mt = 0; mt < 2; mt++)
#pragma unroll
            for (int e = 0; e < 4; e++) acc[mt][e] = 0.f;

        float4 st4[4];
#define STAGE_FETCH(cc)                                                              \
        do {                                                                         \
            _Pragma("unroll")                                                        \
            for (int j = 0; j < 4; j++) {                                            \
                const int idx = tid + j * 256;                                       \
                const int row = idx >> 5, c4 = idx & 31;                             \
                st4[j] = __ldcg((const float4*)(g_hbuf + row * HH + (cc) * 128 + c4 * 4)); \
            }                                                                        \
        } while (0)
#define STAGE_STORE(bf)                                                              \
        do {                                                                         \
            _Pragma("unroll")                                                        \
            for (int j = 0; j < 4; j++) {                                            \
                const int idx = tid + j * 256;                                       \
                const int row = idx >> 5, c4 = idx & 31;                             \
                float* d = sH + (bf) * (32 * SH_STRIDE) + row * SH_STRIDE + c4 * 4;  \
                d[0] = __uint_as_float(tf32r(st4[j].x));                             \
                d[1] = __uint_as_float(tf32r(st4[j].y));                             \
                d[2] = __uint_as_float(tf32r(st4[j].z));                             \
                d[3] = __uint_as_float(tf32r(st4[j].w));                             \
            }                                                                        \
        } while (0)

        STAGE_FETCH(0);
        STAGE_STORE(0);
        __syncthreads();

        for (int cc = 0; cc < 8; cc++) {
            const int cur = cc & 1;
            if (cc < 7) STAGE_FETCH(cc + 1);
            const float* hh = sH + cur * (32 * SH_STRIDE);
#pragma unroll
            for (int s = 0; s < 8; s++) {
                const int k = khalf * 64 + s * 8;
                const int kg = cc * 128 + k;
                unsigned bfr[2];
                bfr[0] = __float_as_uint(sW[(n_off + g) * SW_STRIDE + kg + tg]);
                bfr[1] = __float_as_uint(sW[(n_off + g) * SW_STRIDE + kg + tg + 4]);
#pragma unroll
                for (int mt = 0; mt < 2; mt++) {
                    const int r0 = mt * 16 + g;
                    unsigned afr[4];
                    afr[0] = __float_as_uint(hh[r0 * SH_STRIDE + k + tg]);
                    afr[1] = __float_as_uint(hh[(r0 + 8) * SH_STRIDE + k + tg]);
                    afr[2] = __float_as_uint(hh[r0 * SH_STRIDE + k + tg + 4]);
                    afr[3] = __float_as_uint(hh[(r0 + 8) * SH_STRIDE + k + tg + 4]);
                    mma8(acc[mt], afr, bfr, acc[mt]);
                }
            }
            if (cc < 7) STAGE_STORE(cur ^ 1);
            __syncthreads();
        }
#undef STAGE_FETCH
#undef STAGE_STORE

        // write K-split partial sums
        {
            float* P = sP + khalf * 1024;
#pragma unroll
            for (int mt = 0; mt < 2; mt++) {
                const int r0 = mt * 16 + g;
                const int c0 = n_off + 2 * tg;
                P[r0 * 32 + c0]           = acc[mt][0];
                P[r0 * 32 + c0 + 1]       = acc[mt][1];
                P[(r0 + 8) * 32 + c0]     = acc[mt][2];
                P[(r0 + 8) * 32 + c0 + 1] = acc[mt][3];
            }
        }
        __syncthreads();

        // cell update: thread handles (batch b, unit u)
        const float p0 = sP[b * 32 + u]      + sP[1024 + b * 32 + u]      + xp0;
        const float p1 = sP[b * 32 + 8 + u]  + sP[1024 + b * 32 + 8 + u]  + xp1;
        const float p2 = sP[b * 32 + 16 + u] + sP[1024 + b * 32 + 16 + u] + xp2;
        const float p3 = sP[b * 32 + 24 + u] + sP[1024 + b * 32 + 24 + u] + xp3;
        const float ii = 1.f / (1.f + expf(-p0));
        const float ff = 1.f / (1.f + expf(-p1));
        const float gg = tanhf(p2);
        const float oo = 1.f / (1.f + expf(-p3));
        c_state = ff * c_state + ii * gg;
        const float h = oo * tanhf(c_state);

        g_hbuf[b * HH + ubase + u] = h;
        const size_t oidx = (size_t)(b * TT + t) * HH + ubase + u;
        if (has_resid)
            seq_out[oidx] = __ldg(resid + oidx) + h;
        else
            seq_out[oidx] = h;

        grid_barrier(++bt);
    }
}

// ---------------- launch -----------------------------------------------------
extern "C" void kernel_launch(void* const* d_in, const int* in_sizes, int n_in,
                              void* d_out, int out_size) {
    const float* x    = (const float*)d_in[0];
    const float* Wih0 = (const float*)d_in[1];
    const float* Whh0 = (const float*)d_in[2];
    const float* bih0 = (const float*)d_in[3];
    const float* bhh0 = (const float*)d_in[4];
    const float* Wih1 = (const float*)d_in[5];
    const float* Whh1 = (const float*)d_in[6];
    const float* bih1 = (const float*)d_in[7];
    const float* bhh1 = (const float*)d_in[8];
    float* out = (float*)d_out;

    void *xgp = nullptr, *h0p = nullptr, *barp = nullptr;
    cudaGetSymbolAddress(&xgp, g_xg);
    cudaGetSymbolAddress(&h0p, g_h0);
    cudaGetSymbolAddress(&barp, g_bar);

    cudaFuncSetAttribute(lstm_layer_kernel,
                         cudaFuncAttributeMaxDynamicSharedMemorySize, SMEM_LSTM_BYTES);

    dim3 gg(32, 128);  // N/128, M/128 for M=16384, N=4096

    // layer 0
    cudaMemsetAsync(barp, 0, 2 * sizeof(unsigned));
    gemm_xw_bias<<<gg, 256>>>(x, Wih0, bih0, bhh0, (float*)xgp);
    lstm_layer_kernel<<<LSTM_NCTA, 256, SMEM_LSTM_BYTES>>>(
        (const float*)xgp, Whh0, (float*)h0p, nullptr, 0);

    // layer 1 (+ residual)
    cudaMemsetAsync(barp, 0, 2 * sizeof(unsigned));
    gemm_xw_bias<<<gg, 256>>>((const float*)h0p, Wih1, bih1, bhh1, (float*)xgp);
    lstm_layer_kernel<<<LSTM_NCTA, 256, SMEM_LSTM_BYTES>>>(
        (const float*)xgp, Whh1, out, (const float*)h0p, 1);
}

// round 9
// speedup vs baseline: 1.2144x; 1.2144x over previous
#include <cuda_runtime.h>
#include <cstdint>

// Problem constants
#define BB 32
#define TT 512
#define HH 1024
#define G4 4096   // 4*H

// ---------------- scratch (static device memory; no allocs allowed) ---------
__device__ float g_xg[(size_t)16384 * 4096];   // [B*T, 4H] pre-activations (reused by both layers)
__device__ float g_h0[(size_t)16384 * 1024];   // layer-0 hidden sequence [B*T, H]
__device__ float g_hbuf[BB * HH];              // current h broadcast buffer [32,1024] (tf32-rounded)
__device__ unsigned g_bar[2];                  // {count, generation}

// ---------------- helpers ---------------------------------------------------
__device__ __forceinline__ unsigned tf32r(float f) {
    unsigned r;
    asm("cvt.rna.tf32.f32 %0, %1;" : "=r"(r) : "f"(f));
    return r;
}

__device__ __forceinline__ void mma8(float* d, const unsigned* a, const unsigned* b, const float* c) {
    asm volatile(
        "mma.sync.aligned.m16n8k8.row.col.f32.tf32.tf32.f32 "
        "{%0,%1,%2,%3},{%4,%5,%6,%7},{%8,%9},{%10,%11,%12,%13};\n"
        : "=f"(d[0]), "=f"(d[1]), "=f"(d[2]), "=f"(d[3])
        : "r"(a[0]), "r"(a[1]), "r"(a[2]), "r"(a[3]),
          "r"(b[0]), "r"(b[1]),
          "f"(c[0]), "f"(c[1]), "f"(c[2]), "f"(c[3]));
}

__device__ __forceinline__ void cp16(uint32_t saddr, const void* gaddr) {
    asm volatile("cp.async.cg.shared.global [%0], [%1], 16;\n" :: "r"(saddr), "l"(gaddr));
}
__device__ __forceinline__ void cp_commit() {
    asm volatile("cp.async.commit_group;\n");
}
template <int N>
__device__ __forceinline__ void cp_wait() {
    asm volatile("cp.async.wait_group %0;\n" :: "n"(N));
}

__device__ __forceinline__ void grid_barrier(unsigned target) {
    __threadfence();
    __syncthreads();
    if (threadIdx.x == 0) {
        unsigned old = atomicAdd(&g_bar[0], 1u);
        if (old == gridDim.x - 1) {
            atomicExch(&g_bar[0], 0u);
            __threadfence();
            atomicExch(&g_bar[1], target);
        } else {
            while (*((volatile unsigned*)&g_bar[1]) < target) { }
        }
    }
    __syncthreads();
}

// ---------------- big GEMM: C[M,4096] = A[M,1024] @ W[4096,1024]^T + (b1+b2) -
// BM=128, BN=128, BK=16, 256 threads, tf32 mma, double-buffered smem.
__global__ __launch_bounds__(256)
void gemm_xw_bias(const float* __restrict__ A, const float* __restrict__ W,
                  const float* __restrict__ b1, const float* __restrict__ b2,
                  float* __restrict__ C) {
    const int K = 1024, N = 4096;
    __shared__ float sA[2][128][20];
    __shared__ float sB[2][128][20];

    const int tid = threadIdx.x;
    const int mBase = blockIdx.y * 128, nBase = blockIdx.x * 128;
    const int warp = tid >> 5, lane = tid & 31;
    const int g = lane >> 2, tg = lane & 3;
    const int m_off = (warp & 3) * 32;   // 4 warps along M
    const int n_off = (warp >> 2) * 64;  // 2 warps along N

    float acc[2][8][4];
#pragma unroll
    for (int mt = 0; mt < 2; mt++)
#pragma unroll
        for (int nt = 0; nt < 8; nt++)
#pragma unroll
            for (int e = 0; e < 4; e++) acc[mt][nt][e] = 0.f;

    float4 ra[2], rb[2];
    const int row0 = tid >> 2, c40 = tid & 3;           // j=0 mapping
    const int row1 = (tid + 256) >> 2, c41 = tid & 3;   // j=1 mapping

#define FETCH(kt)                                                                     \
    do {                                                                              \
        ra[0] = *(const float4*)(A + (size_t)(mBase + row0) * K + (kt) * 16 + c40*4); \
        rb[0] = *(const float4*)(W + (size_t)(nBase + row0) * K + (kt) * 16 + c40*4); \
        ra[1] = *(const float4*)(A + (size_t)(mBase + row1) * K + (kt) * 16 + c41*4); \
        rb[1] = *(const float4*)(W + (size_t)(nBase + row1) * K + (kt) * 16 + c41*4); \
    } while (0)

#define STORE(bf)                                                                 \
    do {                                                                          \
        float* pa0 = &sA[bf][row0][c40 * 4]; float* pb0 = &sB[bf][row0][c40 * 4]; \
        pa0[0]=__uint_as_float(tf32r(ra[0].x)); pa0[1]=__uint_as_float(tf32r(ra[0].y)); \
        pa0[2]=__uint_as_float(tf32r(ra[0].z)); pa0[3]=__uint_as_float(tf32r(ra[0].w)); \
        pb0[0]=__uint_as_float(tf32r(rb[0].x)); pb0[1]=__uint_as_float(tf32r(rb[0].y)); \
        pb0[2]=__uint_as_float(tf32r(rb[0].z)); pb0[3]=__uint_as_float(tf32r(rb[0].w)); \
        float* pa1 = &sA[bf][row1][c41 * 4]; float* pb1 = &sB[bf][row1][c41 * 4]; \
        pa1[0]=__uint_as_float(tf32r(ra[1].x)); pa1[1]=__uint_as_float(tf32r(ra[1].y)); \
        pa1[2]=__uint_as_float(tf32r(ra[1].z)); pa1[3]=__uint_as_float(tf32r(ra[1].w)); \
        pb1[0]=__uint_as_float(tf32r(rb[1].x)); pb1[1]=__uint_as_float(tf32r(rb[1].y)); \
        pb1[2]=__uint_as_float(tf32r(rb[1].z)); pb1[3]=__uint_as_float(tf32r(rb[1].w)); \
    } while (0)

    FETCH(0);
    STORE(0);
    __syncthreads();

    for (int kt = 0; kt < 64; kt++) {
        const int cur = kt & 1;
        if (kt < 63) FETCH(kt + 1);
#pragma unroll
        for (int ks = 0; ks < 2; ks++) {
            const int k0 = ks * 8;
            unsigned afr[2][4], bfr[8][2];
#pragma unroll
            for (int mt = 0; mt < 2; mt++) {
                const int r = m_off + mt * 16 + g;
                afr[mt][0] = __float_as_uint(sA[cur][r][k0 + tg]);
                afr[mt][1] = __float_as_uint(sA[cur][r + 8][k0 + tg]);
                afr[mt][2] = __float_as_uint(sA[cur][r][k0 + tg + 4]);
                afr[mt][3] = __float_as_uint(sA[cur][r + 8][k0 + tg + 4]);
            }
#pragma unroll
            for (int nt = 0; nt < 8; nt++) {
                const int n = n_off + nt * 8 + g;
                bfr[nt][0] = __float_as_uint(sB[cur][n][k0 + tg]);
                bfr[nt][1] = __float_as_uint(sB[cur][n][k0 + tg + 4]);
            }
#pragma unroll
            for (int mt = 0; mt < 2; mt++)
#pragma unroll
                for (int nt = 0; nt < 8; nt++)
                    mma8(acc[mt][nt], afr[mt], bfr[nt], acc[mt][nt]);
        }
        if (kt < 63) STORE(cur ^ 1);
        __syncthreads();
    }
#undef FETCH
#undef STORE

    // epilogue: += (b1+b2)
#pragma unroll
    for (int mt = 0; mt < 2; mt++) {
#pragma unroll
        for (int nt = 0; nt < 8; nt++) {
            const int r0 = mBase + m_off + mt * 16 + g;
            const int c0 = nBase + n_off + nt * 8 + 2 * tg;
            const float bs0 = __ldg(b1 + c0) + __ldg(b2 + c0);
            const float bs1 = __ldg(b1 + c0 + 1) + __ldg(b2 + c0 + 1);
            C[(size_t)r0 * N + c0]           = acc[mt][nt][0] + bs0;
            C[(size_t)r0 * N + c0 + 1]       = acc[mt][nt][1] + bs1;
            C[(size_t)(r0 + 8) * N + c0]     = acc[mt][nt][2] + bs0;
            C[(size_t)(r0 + 8) * N + c0 + 1] = acc[mt][nt][3] + bs1;
        }
    }
}

// ---------------- persistent LSTM layer -------------------------------------
// 128 CTAs (1/SM, all resident), 256 threads. CTA c owns hidden units
// [c*8, c*8+8) -> 32 gate columns {gi*1024 + ubase + u}. Whh slice cached in
// SMEM (tf32-rounded once). Per step: h broadcast is streamed from L2 via a
// 4-deep cp.async pipeline (no register round-trip; h is stored tf32-rounded
// at the producer so no stage-time conversion is needed), recurrent GEMM via
// tf32 mma with 2 accumulation chains, cell update, h broadcast, grid barrier.
#define LSTM_NCTA 128
#define SW_STRIDE 1028
#define SH_STRIDE 132
#define LSTM_PIPE 4
#define SMEM_LSTM_FLOATS (32 * SW_STRIDE + LSTM_PIPE * 32 * SH_STRIDE + 2 * 32 * 32)
#define SMEM_LSTM_BYTES (SMEM_LSTM_FLOATS * 4)

__global__ __launch_bounds__(256)
void lstm_layer_kernel(const float* __restrict__ xg, const float* __restrict__ Whh,
                       float* __restrict__ seq_out, const float* __restrict__ resid,
                       int has_resid) {
    extern __shared__ float sm[];
    float* sW = sm;                               // [32][1028]
    float* sH = sW + 32 * SW_STRIDE;              // [4][32][132]  cp.async ring
    float* sP = sH + LSTM_PIPE * 32 * SH_STRIDE; // [2][32][32]

    const int tid = threadIdx.x;
    const int warp = tid >> 5, lane = tid & 31;
    const int g = lane >> 2, tg = lane & 3;
    const int n_off = (warp & 3) * 8;
    const int khalf = warp >> 2;
    const int ubase = blockIdx.x * 8;
    const int b = tid >> 3, u = tid & 7;

    const uint32_t sH_u32 = (uint32_t)__cvta_generic_to_shared(sH);
    // per-thread fixed staging coordinates (idx = tid + j*256)
    const int st_row0 = tid >> 5,           st_c0 = tid & 31;
    const int st_row1 = (tid + 256) >> 5,   st_c1 = tid & 31;
    const int st_row2 = (tid + 512) >> 5,   st_c2 = tid & 31;
    const int st_row3 = (tid + 768) >> 5,   st_c3 = tid & 31;

    // load + tf32-round the Whh slice (32 rows x 1024) into smem
    for (int i = tid; i < 32 * 256; i += 256) {
        const int col = i >> 8;      // 0..31
        const int f4 = i & 255;      // 0..255
        const int grow = (col >> 3) * 1024 + ubase + (col & 7);
        float4 v = *(const float4*)(Whh + (size_t)grow * 1024 + f4 * 4);
        float* dst = sW + col * SW_STRIDE + f4 * 4;
        dst[0] = __uint_as_float(tf32r(v.x));
        dst[1] = __uint_as_float(tf32r(v.y));
        dst[2] = __uint_as_float(tf32r(v.z));
        dst[3] = __uint_as_float(tf32r(v.w));
    }
    // zero my slice of the h broadcast buffer
    g_hbuf[b * HH + ubase + u] = 0.f;

    unsigned bt = 0;
    grid_barrier(++bt);

    float c_state = 0.f;

#define ISSUE(chunk)                                                                   \
    do {                                                                               \
        const uint32_t sb = sH_u32 + ((chunk) & 3) * (32 * SH_STRIDE * 4);             \
        cp16(sb + (st_row0 * SH_STRIDE + st_c0 * 4) * 4,                               \
             g_hbuf + st_row0 * HH + (chunk) * 128 + st_c0 * 4);                       \
        cp16(sb + (st_row1 * SH_STRIDE + st_c1 * 4) * 4,                               \
             g_hbuf + st_row1 * HH + (chunk) * 128 + st_c1 * 4);                       \
        cp16(sb + (st_row2 * SH_STRIDE + st_c2 * 4) * 4,                               \
             g_hbuf + st_row2 * HH + (chunk) * 128 + st_c2 * 4);                       \
        cp16(sb + (st_row3 * SH_STRIDE + st_c3 * 4) * 4,                               \
             g_hbuf + st_row3 * HH + (chunk) * 128 + st_c3 * 4);                       \
        cp_commit();                                                                   \
    } while (0)

#define MMA_CHUNK(cc)                                                                  \
    do {                                                                               \
        const float* hh = sH + ((cc) & 3) * (32 * SH_STRIDE);                          \
        _Pragma("unroll")                                                              \
        for (int s = 0; s < 8; s++) {                                                  \
            const int k = khalf * 64 + s * 8;                                          \
            const int kg = (cc) * 128 + k;                                             \
            unsigned bfr[2];                                                           \
            bfr[0] = __float_as_uint(sW[(n_off + g) * SW_STRIDE + kg + tg]);           \
            bfr[1] = __float_as_uint(sW[(n_off + g) * SW_STRIDE + kg + tg + 4]);       \
            _Pragma("unroll")                                                          \
            for (int mt = 0; mt < 2; mt++) {                                           \
                const int r0 = mt * 16 + g;                                            \
                unsigned afr[4];                                                       \
                afr[0] = __float_as_uint(hh[r0 * SH_STRIDE + k + tg]);                 \
                afr[1] = __float_as_uint(hh[(r0 + 8) * SH_STRIDE + k + tg]);           \
                afr[2] = __float_as_uint(hh[r0 * SH_STRIDE + k + tg + 4]);             \
                afr[3] = __float_as_uint(hh[(r0 + 8) * SH_STRIDE + k + tg + 4]);       \
                mma8(acc[mt][s & 1], afr, bfr, acc[mt][s & 1]);                        \
            }                                                                          \
        }                                                                              \
    } while (0)

    for (int t = 0; t < TT; t++) {
        // prefetch this thread's 4 gate pre-activations + residual (DRAM; consumed at step end)
        const size_t xrow = (size_t)(b * TT + t) * G4;
        const float xp0 = __ldg(xg + xrow + 0 * HH + ubase + u);
        const float xp1 = __ldg(xg + xrow + 1 * HH + ubase + u);
        const float xp2 = __ldg(xg + xrow + 2 * HH + ubase + u);
        const float xp3 = __ldg(xg + xrow + 3 * HH + ubase + u);
        const size_t oidx = (size_t)(b * TT + t) * HH + ubase + u;
        const float rres = has_resid ? __ldg(resid + oidx) : 0.f;

        float acc[2][2][4];
#pragma unroll
        for (int mt = 0; mt < 2; mt++)
#pragma unroll
            for (int p = 0; p < 2; p++)
#pragma unroll
                for (int e = 0; e < 4; e++) acc[mt][p][e] = 0.f;

        // 4-deep cp.async pipeline over the 8 h-chunks.
        ISSUE(0); ISSUE(1); ISSUE(2); ISSUE(3);

        cp_wait<3>(); __syncthreads();            MMA_CHUNK(0);
        cp_wait<2>(); __syncthreads(); ISSUE(4);  MMA_CHUNK(1);
        cp_wait<2>(); __syncthreads(); ISSUE(5);  MMA_CHUNK(2);
        cp_wait<2>(); __syncthreads(); ISSUE(6);  MMA_CHUNK(3);
        cp_wait<2>(); __syncthreads(); ISSUE(7);  MMA_CHUNK(4);
        cp_wait<2>(); __syncthreads();            MMA_CHUNK(5);
        cp_wait<1>(); __syncthreads();            MMA_CHUNK(6);
        cp_wait<0>(); __syncthreads();            MMA_CHUNK(7);

        // write K-split partial sums (combine the two accumulation chains)
        {
            float* P = sP + khalf * 1024;
#pragma unroll
            for (int mt = 0; mt < 2; mt++) {
                const int r0 = mt * 16 + g;
                const int c0 = n_off + 2 * tg;
                P[r0 * 32 + c0]           = acc[mt][0][0] + acc[mt][1][0];
                P[r0 * 32 + c0 + 1]       = acc[mt][0][1] + acc[mt][1][1];
                P[(r0 + 8) * 32 + c0]     = acc[mt][0][2] + acc[mt][1][2];
                P[(r0 + 8) * 32 + c0 + 1] = acc[mt][0][3] + acc[mt][1][3];
            }
        }
        __syncthreads();

        // cell update: thread handles (batch b, unit u)
        const float p0 = sP[b * 32 + u]      + sP[1024 + b * 32 + u]      + xp0;
        const float p1 = sP[b * 32 + 8 + u]  + sP[1024 + b * 32 + 8 + u]  + xp1;
        const float p2 = sP[b * 32 + 16 + u] + sP[1024 + b * 32 + 16 + u] + xp2;
        const float p3 = sP[b * 32 + 24 + u] + sP[1024 + b * 32 + 24 + u] + xp3;
        const float ii = 1.f / (1.f + expf(-p0));
        const float ff = 1.f / (1.f + expf(-p1));
        const float gg = tanhf(p2);
        const float oo = 1.f / (1.f + expf(-p3));
        c_state = ff * c_state + ii * gg;
        const float h = oo * tanhf(c_state);

        // broadcast h pre-rounded to tf32 (rna) — staging then needs no conversion
        g_hbuf[b * HH + ubase + u] = __uint_as_float(tf32r(h));
        seq_out[oidx] = rres + h;   // rres == 0 when no residual

        grid_barrier(++bt);
    }
#undef ISSUE
#undef MMA_CHUNK
}

// ---------------- launch -----------------------------------------------------
extern "C" void kernel_launch(void* const* d_in, const int* in_sizes, int n_in,
                              void* d_out, int out_size) {
    const float* x    = (const float*)d_in[0];
    const float* Wih0 = (const float*)d_in[1];
    const float* Whh0 = (const float*)d_in[2];
    const float* bih0 = (const float*)d_in[3];
    const float* bhh0 = (const float*)d_in[4];
    const float* Wih1 = (const float*)d_in[5];
    const float* Whh1 = (const float*)d_in[6];
    const float* bih1 = (const float*)d_in[7];
    const float* bhh1 = (const float*)d_in[8];
    float* out = (float*)d_out;

    void *xgp = nullptr, *h0p = nullptr, *barp = nullptr;
    cudaGetSymbolAddress(&xgp, g_xg);
    cudaGetSymbolAddress(&h0p, g_h0);
    cudaGetSymbolAddress(&barp, g_bar);

    cudaFuncSetAttribute(lstm_layer_kernel,
                         cudaFuncAttributeMaxDynamicSharedMemorySize, SMEM_LSTM_BYTES);

    dim3 gg(32, 128);  // N/128, M/128 for M=16384, N=4096

    // layer 0
    cudaMemsetAsync(barp, 0, 2 * sizeof(unsigned));
    gemm_xw_bias<<<gg, 256>>>(x, Wih0, bih0, bhh0, (float*)xgp);
    lstm_layer_kernel<<<LSTM_NCTA, 256, SMEM_LSTM_BYTES>>>(
        (const float*)xgp, Whh0, (float*)h0p, nullptr, 0);

    // layer 1 (+ residual)
    cudaMemsetAsync(barp, 0, 2 * sizeof(unsigned));
    gemm_xw_bias<<<gg, 256>>>((const float*)h0p, Wih1, bih1, bhh1, (float*)xgp);
    lstm_layer_kernel<<<LSTM_NCTA, 256, SMEM_LSTM_BYTES>>>(
        (const float*)xgp, Whh1, out, (const float*)h0p, 1);
}